// round 3
// baseline (speedup 1.0000x reference)
#include <cuda_runtime.h>
#include <cstdint>

#define BSZ    256
#define FEAT   128
#define KP1    4097
#define PAD    4100
#define NDATA  500000
#define SDIM   1024
#define TDIM   2048
#define MEMELEMS 64000000
#define TOTAL  (BSZ * KP1)     // 1,048,832
#define EPSF   1e-7f
#define MPN    (4096.0f / 500000.0f)
#define N4     15999999        // float4 chunks in shifted copy
#define NCE_BLOCKS 4097
#define MEGA_BLOCKS (NCE_BLOCKS * 5)       // 20485
#define COPY_SLOTS  (NCE_BLOCKS * 4)       // 16388
#define COPY_T      (COPY_SLOTS * 256)     // 4,195,328
#define LOSS_BLOCKS 1280                   // 5 x 256

__device__ float g_es[BSZ * FEAT];
__device__ float g_et[BSZ * FEAT];
__device__ float g_out_s[BSZ * PAD];
__device__ float g_out_t[BSZ * PAD];
__device__ float g_sums[3];
__device__ int   g_ticket;

// ---------------------------------------------------------------- embeddings (+init)
__global__ void embed_kernel(const float* __restrict__ f_s, const float* __restrict__ f_t,
                             const float* __restrict__ W_s, const float* __restrict__ b_s,
                             const float* __restrict__ W_t, const float* __restrict__ b_t) {
    if (blockIdx.x == 0 && threadIdx.x == 0) {
        g_sums[0] = 0.f; g_sums[1] = 0.f; g_sums[2] = 0.f; g_ticket = 0;
    }
    __shared__ float fsh[4 * 2048];
    __shared__ float sh[4];
    const bool is_t = blockIdx.x >= 64;
    const int  rb   = (is_t ? blockIdx.x - 64 : blockIdx.x) * 4;
    const float* f    = is_t ? f_t : f_s;
    const float* W    = is_t ? W_t : W_s;
    const float* bias = is_t ? b_t : b_s;
    float*       out  = is_t ? g_et : g_es;
    const int    Kd   = is_t ? TDIM : SDIM;
    const int t = threadIdx.x;

    #pragma unroll
    for (int r = 0; r < 4; ++r)
        for (int k = t; k < Kd; k += 128)
            fsh[r * 2048 + k] = f[(rb + r) * Kd + k];
    __syncthreads();

    float a0 = 0.f, a1 = 0.f, a2 = 0.f, a3 = 0.f;
    for (int k = 0; k < Kd; ++k) {
        float w = W[k * FEAT + t];
        a0 += fsh[k] * w;
        a1 += fsh[2048 + k] * w;
        a2 += fsh[4096 + k] * w;
        a3 += fsh[6144 + k] * w;
    }
    const float bb = bias[t];
    float acc[4] = {a0 + bb, a1 + bb, a2 + bb, a3 + bb};

    const int lane = t & 31, w_ = t >> 5;
    #pragma unroll
    for (int r = 0; r < 4; ++r) {
        float v = acc[r] * acc[r];
        #pragma unroll
        for (int o = 16; o; o >>= 1) v += __shfl_xor_sync(0xffffffffu, v, o);
        if (lane == 0) sh[w_] = v;
        __syncthreads();
        float tot = sh[0] + sh[1] + sh[2] + sh[3];
        __syncthreads();
        out[(rb + r) * FEAT + t] = acc[r] / sqrtf(tot);
    }
}

// ---------------------------------------------------------------- MEGA: copy + nce fused
// bid % 5 == 0  -> nce block (4097 of them)
// else          -> copy block (16388 slots)
__global__ __launch_bounds__(256) void mega_kernel(const int* __restrict__ cidx,
                                                   const float* __restrict__ m1,
                                                   const float* __restrict__ m2,
                                                   float* __restrict__ out) {
    const int bid = blockIdx.x;

    if (bid % 5 != 0) {
        // ---------------- copy role ----------------
        const int slot = bid - bid / 5 - 1;
        const int tid = slot * 256 + threadIdx.x;
        float4* o1b = (float4*)(out + 4);
        float4* o2b = (float4*)(out + 4 + MEMELEMS);
        #pragma unroll
        for (int s = 0; s < 4; ++s) {
            const int i = tid + s * COPY_T;
            if (i < N4) {
                float  h1 = __ldg(m1 + 3 + 4 * i);
                float4 v1 = __ldg((const float4*)(m1 + 4 + 4 * i));
                float  h2 = __ldg(m2 + 3 + 4 * i);
                float4 v2 = __ldg((const float4*)(m2 + 4 + 4 * i));
                o1b[i] = make_float4(h1, v1.x, v1.y, v1.z);
                o2b[i] = make_float4(h2, v2.x, v2.y, v2.z);
            }
        }
        if (slot == 0 && threadIdx.x == 0) {
            out[1] = m1[0]; out[2] = m1[1]; out[3] = m1[2];
            out[MEMELEMS] = m1[MEMELEMS - 1];
            out[1 + MEMELEMS] = m2[0]; out[2 + MEMELEMS] = m2[1]; out[3 + MEMELEMS] = m2[2];
            out[2 * MEMELEMS] = m2[MEMELEMS - 1];
        }
        return;
    }

    // ---------------- nce role ----------------
    const int lane = threadIdx.x & 31;
    const int wInB = threadIdx.x >> 5;
    const int wid  = (bid / 5) * 8 + wInB;       // 0 .. 32775
    const int t0   = wid * 32;

    int b = t0 / KP1;
    int k = t0 - b * KP1;
    int bcur = b;
    float4 es4 = *((const float4*)(g_es + b * FEAT) + lane);
    float4 et4 = *((const float4*)(g_et + b * FEAT) + lane);
    float sumT = 0.f, sumS = 0.f;

    #pragma unroll 1
    for (int g = 0; g < 8; ++g) {
        int rows[4], bs[4], ks[4];
        #pragma unroll
        for (int j = 0; j < 4; ++j) {
            rows[j] = __ldg(cidx + t0 + g * 4 + j);
            bs[j] = b; ks[j] = k;
            if (++k == KP1) { k = 0; ++b; }
        }
        float4 A[4], C[4];
        #pragma unroll
        for (int j = 0; j < 4; ++j) {
            A[j] = __ldg((const float4*)m1 + (size_t)rows[j] * 32 + lane);
            C[j] = __ldg((const float4*)m2 + (size_t)rows[j] * 32 + lane);
        }
        float dt[4], ds[4];
        #pragma unroll
        for (int j = 0; j < 4; ++j) {
            if (bs[j] != bcur) {
                bcur = bs[j];
                es4 = *((const float4*)(g_es + bcur * FEAT) + lane);
                et4 = *((const float4*)(g_et + bcur * FEAT) + lane);
            }
            dt[j] = A[j].x * et4.x + A[j].y * et4.y + A[j].z * et4.z + A[j].w * et4.w;
            ds[j] = C[j].x * es4.x + C[j].y * es4.y + C[j].z * es4.z + C[j].w * es4.w;
        }
        #pragma unroll
        for (int o = 16; o; o >>= 1) {
            #pragma unroll
            for (int j = 0; j < 4; ++j) {
                dt[j] += __shfl_xor_sync(0xffffffffu, dt[j], o);
                ds[j] += __shfl_xor_sync(0xffffffffu, ds[j], o);
            }
        }
        if (lane == 0) {
            #pragma unroll
            for (int j = 0; j < 4; ++j) {
                float ot = __expf(dt[j] * (1.0f / 0.07f));
                float os = __expf(ds[j] * (1.0f / 0.07f));
                g_out_t[bs[j] * PAD + ks[j]] = ot;
                g_out_s[bs[j] * PAD + ks[j]] = os;
                sumT += ot; sumS += os;
            }
        }
    }

    __shared__ float shT[8], shS[8];
    if (lane == 0) { shT[wInB] = sumT; shS[wInB] = sumS; }
    __syncthreads();
    if (threadIdx.x == 0) {
        float aT = 0.f, aS = 0.f;
        #pragma unroll
        for (int i = 0; i < 8; ++i) { aT += shT[i]; aS += shS[i]; }
        atomicAdd(&g_sums[0], aT);
        atomicAdd(&g_sums[1], aS);
    }
}

// ---------------------------------------------------------------- loss + update + finalize
// blocks [0, 1280): loss, b = bid/5, chunk = bid%5
// blocks [1280, 1536): update row b = bid - 1280 (uses first 128 threads)
__global__ __launch_bounds__(256) void lossup_kernel(const int* __restrict__ idx,
                                                     const float* __restrict__ m1,
                                                     const float* __restrict__ m2,
                                                     float* __restrict__ out) {
    const int bid = blockIdx.x;
    if (bid < LOSS_BLOCKS) {
        const int b = bid / 5;
        const int k = ((bid % 5) * 256 + threadIdx.x) * 4;
        const float invZt = (float)TOTAL / ((float)NDATA * g_sums[0]);
        const float invZs = (float)TOTAL / ((float)NDATA * g_sums[1]);
        float acc = 0.f;
        if (k < KP1) {
            float4 vs = *((const float4*)(g_out_s + b * PAD + k));
            float4 vt = *((const float4*)(g_out_t + b * PAD + k));
            float xs[4] = {vs.x, vs.y, vs.z, vs.w};
            float xt[4] = {vt.x, vt.y, vt.z, vt.w};
            #pragma unroll
            for (int c = 0; c < 4; ++c) {
                if (k + c < KP1) {
                    float xS = xs[c] * invZs;
                    float xT = xt[c] * invZt;
                    if (k + c == 0) {
                        acc += logf(xS / (xS + MPN + EPSF)) + logf(xT / (xT + MPN + EPSF));
                    } else {
                        acc -= logf(1.0f + (xS + EPSF) * (1.0f / MPN));
                        acc -= logf(1.0f + (xT + EPSF) * (1.0f / MPN));
                    }
                }
            }
        }
        #pragma unroll
        for (int o = 16; o; o >>= 1) acc += __shfl_xor_sync(0xffffffffu, acc, o);
        __shared__ float sh[8];
        const int lane = threadIdx.x & 31, w_ = threadIdx.x >> 5;
        if (lane == 0) sh[w_] = acc;
        __syncthreads();
        if (threadIdx.x == 0) {
            float tot = 0.f;
            #pragma unroll
            for (int i = 0; i < 8; ++i) tot += sh[i];
            atomicAdd(&g_sums[2], tot);
            __threadfence();
            int t = atomicAdd(&g_ticket, 1);
            if (t == LOSS_BLOCKS - 1) {
                out[0] = -g_sums[2] / (float)BSZ;
            }
        }
        return;
    }

    // ---------------- update role ----------------
    const int b = bid - LOSS_BLOCKS;
    const int t = threadIdx.x;
    if (t >= 128) return;
    float* o1 = out + 1;
    float* o2 = out + 1 + MEMELEMS;
    const int row = __ldg(idx + b);
    const size_t off = (size_t)row * FEAT + t;
    float v1 = __ldg(m1 + off) * 0.5f + g_es[b * FEAT + t] * 0.5f;
    float v2 = __ldg(m2 + off) * 0.5f + g_et[b * FEAT + t] * 0.5f;
    float s1 = v1 * v1, s2 = v2 * v2;
    #pragma unroll
    for (int o = 16; o; o >>= 1) {
        s1 += __shfl_xor_sync(0xffffffffu, s1, o);
        s2 += __shfl_xor_sync(0xffffffffu, s2, o);
    }
    __shared__ float sh1[4], sh2[4];
    const int lane = t & 31, w_ = t >> 5;
    if (lane == 0) { sh1[w_] = s1; sh2[w_] = s2; }
    __syncthreads();
    float t1 = sh1[0] + sh1[1] + sh1[2] + sh1[3];
    float t2 = sh2[0] + sh2[1] + sh2[2] + sh2[3];
    o1[off] = v1 / sqrtf(t1);
    o2[off] = v2 / sqrtf(t2);
}

// ---------------------------------------------------------------- launch
extern "C" void kernel_launch(void* const* d_in, const int* in_sizes, int n_in,
                              void* d_out, int out_size) {
    const float* f_s  = (const float*)d_in[0];
    const float* f_t  = (const float*)d_in[1];
    const int*   idx  = (const int*)  d_in[2];
    const int*   cidx = (const int*)  d_in[3];
    const float* W_s  = (const float*)d_in[4];
    const float* b_s  = (const float*)d_in[5];
    const float* W_t  = (const float*)d_in[6];
    const float* b_t  = (const float*)d_in[7];
    const float* m1   = (const float*)d_in[8];
    const float* m2   = (const float*)d_in[9];
    float* out = (float*)d_out;

    embed_kernel<<<128, 128>>>(f_s, f_t, W_s, b_s, W_t, b_t);
    mega_kernel<<<MEGA_BLOCKS, 256>>>(cidx, m1, m2, out);
    lossup_kernel<<<LOSS_BLOCKS + BSZ, 256>>>(idx, m1, m2, out);
}

// round 4
// speedup vs baseline: 1.6640x; 1.6640x over previous
#include <cuda_runtime.h>
#include <cstdint>

#define BSZ    256
#define FEAT   128
#define KP1    4097
#define PAD    4100
#define NDATA  500000
#define SDIM   1024
#define TDIM   2048
#define MEMELEMS 64000000
#define TOTAL  (BSZ * KP1)
#define EPSF   1e-7f
#define MPN    (4096.0f / 500000.0f)
#define N4     15999999
#define LOSS_BLOCKS 1280
#define KSPLIT 8

__device__ float g_es[BSZ * FEAT];
__device__ float g_et[BSZ * FEAT];
__device__ float g_part_s[KSPLIT * BSZ * FEAT];   // [ks][row][feat]
__device__ float g_part_t[KSPLIT * BSZ * FEAT];
__device__ float g_out_s[BSZ * PAD];
__device__ float g_out_t[BSZ * PAD];
__device__ float g_sums[3];
__device__ int   g_ticket;

// ---------------------------------------------------------------- embed partial (split-K GEMM)
// grid: 1024 blocks. bid<512: s-side (Kd=1024), else t-side (Kd=2048).
// Within side: row-tile = id>>3 (4 rows), ksplit = id&7.
__global__ __launch_bounds__(128) void embed_partial(const float* __restrict__ f_s,
                                                     const float* __restrict__ f_t,
                                                     const float* __restrict__ W_s,
                                                     const float* __restrict__ W_t) {
    __shared__ float fsh[4 * 256];
    const int bid = blockIdx.x;
    const bool is_t = bid >= 512;
    const int id = is_t ? bid - 512 : bid;
    const int rt = id >> 3;
    const int ks = id & 7;
    const int Kd = is_t ? TDIM : SDIM;
    const int kchunk = Kd / KSPLIT;          // 256 or 128
    const int k0 = ks * kchunk;
    const float* f = is_t ? f_t : f_s;
    const float* W = is_t ? W_t : W_s;
    float* part = is_t ? g_part_t : g_part_s;
    const int rows0 = rt * 4;
    const int t = threadIdx.x;

    #pragma unroll
    for (int r = 0; r < 4; ++r)
        for (int k = t; k < kchunk; k += 128)
            fsh[r * 256 + k] = f[(rows0 + r) * Kd + k0 + k];
    __syncthreads();

    float a0 = 0.f, a1 = 0.f, a2 = 0.f, a3 = 0.f;
    const float* Wp = W + (size_t)k0 * FEAT + t;
    #pragma unroll 8
    for (int k = 0; k < kchunk; ++k) {
        float w = Wp[(size_t)k * FEAT];
        a0 += fsh[k] * w;
        a1 += fsh[256 + k] * w;
        a2 += fsh[512 + k] * w;
        a3 += fsh[768 + k] * w;
    }
    float acc[4] = {a0, a1, a2, a3};
    #pragma unroll
    for (int r = 0; r < 4; ++r)
        part[(ks * BSZ + rows0 + r) * FEAT + t] = acc[r];
}

// ---------------------------------------------------------------- normalize (+init)
// grid: 512 blocks (one per row; bid<256 -> s, else t), 128 threads.
__global__ __launch_bounds__(128) void normalize_kernel(const float* __restrict__ b_s,
                                                        const float* __restrict__ b_t) {
    if (blockIdx.x == 0 && threadIdx.x == 0) {
        g_sums[0] = 0.f; g_sums[1] = 0.f; g_sums[2] = 0.f; g_ticket = 0;
    }
    const int bid = blockIdx.x;
    const bool is_t = bid >= 256;
    const int row = is_t ? bid - 256 : bid;
    const float* part = is_t ? g_part_t : g_part_s;
    const float* bias = is_t ? b_t : b_s;
    float* out = is_t ? g_et : g_es;
    const int t = threadIdx.x;

    float v = bias[t];
    #pragma unroll
    for (int ks = 0; ks < KSPLIT; ++ks)
        v += part[(ks * BSZ + row) * FEAT + t];

    float sq = v * v;
    #pragma unroll
    for (int o = 16; o; o >>= 1) sq += __shfl_xor_sync(0xffffffffu, sq, o);
    __shared__ float sh[4];
    const int lane = t & 31, w_ = t >> 5;
    if (lane == 0) sh[w_] = sq;
    __syncthreads();
    float tot = sh[0] + sh[1] + sh[2] + sh[3];
    out[row * FEAT + t] = v / sqrtf(tot);
}

// ---------------------------------------------------------------- NCE gather + dot + exp
__global__ __launch_bounds__(256) void nce_kernel(const int* __restrict__ cidx,
                                                  const float* __restrict__ m1,
                                                  const float* __restrict__ m2) {
    const int lane = threadIdx.x & 31;
    const int wInB = threadIdx.x >> 5;
    const int wid  = (blockIdx.x * blockDim.x + threadIdx.x) >> 5;
    const int t0   = wid * 32;

    int b = t0 / KP1;
    int k = t0 - b * KP1;
    int bcur = b;
    float4 es4 = *((const float4*)(g_es + b * FEAT) + lane);
    float4 et4 = *((const float4*)(g_et + b * FEAT) + lane);
    float sumT = 0.f, sumS = 0.f;

    #pragma unroll 1
    for (int g = 0; g < 8; ++g) {
        int rows[4], bs[4], ks[4];
        #pragma unroll
        for (int j = 0; j < 4; ++j) {
            rows[j] = __ldg(cidx + t0 + g * 4 + j);
            bs[j] = b; ks[j] = k;
            if (++k == KP1) { k = 0; ++b; }
        }
        float4 A[4], C[4];
        #pragma unroll
        for (int j = 0; j < 4; ++j) {
            A[j] = __ldg((const float4*)m1 + (size_t)rows[j] * 32 + lane);
            C[j] = __ldg((const float4*)m2 + (size_t)rows[j] * 32 + lane);
        }
        float dt[4], ds[4];
        #pragma unroll
        for (int j = 0; j < 4; ++j) {
            if (bs[j] != bcur) {
                bcur = bs[j];
                es4 = *((const float4*)(g_es + bcur * FEAT) + lane);
                et4 = *((const float4*)(g_et + bcur * FEAT) + lane);
            }
            dt[j] = A[j].x * et4.x + A[j].y * et4.y + A[j].z * et4.z + A[j].w * et4.w;
            ds[j] = C[j].x * es4.x + C[j].y * es4.y + C[j].z * es4.z + C[j].w * es4.w;
        }
        #pragma unroll
        for (int o = 16; o; o >>= 1) {
            #pragma unroll
            for (int j = 0; j < 4; ++j) {
                dt[j] += __shfl_xor_sync(0xffffffffu, dt[j], o);
                ds[j] += __shfl_xor_sync(0xffffffffu, ds[j], o);
            }
        }
        if (lane == 0) {
            #pragma unroll
            for (int j = 0; j < 4; ++j) {
                float ot = __expf(dt[j] * (1.0f / 0.07f));
                float os = __expf(ds[j] * (1.0f / 0.07f));
                g_out_t[bs[j] * PAD + ks[j]] = ot;
                g_out_s[bs[j] * PAD + ks[j]] = os;
                sumT += ot; sumS += os;
            }
        }
    }

    __shared__ float shT[8], shS[8];
    if (lane == 0) { shT[wInB] = sumT; shS[wInB] = sumS; }
    __syncthreads();
    if (threadIdx.x == 0) {
        float aT = 0.f, aS = 0.f;
        #pragma unroll
        for (int i = 0; i < 8; ++i) { aT += shT[i]; aS += shS[i]; }
        atomicAdd(&g_sums[0], aT);
        atomicAdd(&g_sums[1], aS);
    }
}

// ---------------------------------------------------------------- memory copy-out
__global__ __launch_bounds__(256) void copy_kernel(const float* __restrict__ m1,
                                                   const float* __restrict__ m2,
                                                   float* __restrict__ out) {
    const int tid = blockIdx.x * blockDim.x + threadIdx.x;
    const int T = gridDim.x * blockDim.x;   // 4,000,000
    float4* o1b = (float4*)(out + 4);
    float4* o2b = (float4*)(out + 4 + MEMELEMS);
    #pragma unroll
    for (int s = 0; s < 4; ++s) {
        const int i = tid + s * T;
        if (i < N4) {
            float  h1 = __ldg(m1 + 3 + 4 * i);
            float4 v1 = __ldg((const float4*)(m1 + 4 + 4 * i));
            float  h2 = __ldg(m2 + 3 + 4 * i);
            float4 v2 = __ldg((const float4*)(m2 + 4 + 4 * i));
            o1b[i] = make_float4(h1, v1.x, v1.y, v1.z);
            o2b[i] = make_float4(h2, v2.x, v2.y, v2.z);
        }
    }
    if (tid == 0) {
        out[1] = m1[0]; out[2] = m1[1]; out[3] = m1[2];
        out[MEMELEMS] = m1[MEMELEMS - 1];
        out[1 + MEMELEMS] = m2[0]; out[2 + MEMELEMS] = m2[1]; out[3 + MEMELEMS] = m2[2];
        out[2 * MEMELEMS] = m2[MEMELEMS - 1];
    }
}

// ---------------------------------------------------------------- loss + update + finalize
__global__ __launch_bounds__(256) void lossup_kernel(const int* __restrict__ idx,
                                                     const float* __restrict__ m1,
                                                     const float* __restrict__ m2,
                                                     float* __restrict__ out) {
    const int bid = blockIdx.x;
    if (bid < LOSS_BLOCKS) {
        const int b = bid / 5;
        const int k = ((bid % 5) * 256 + threadIdx.x) * 4;
        const float invZt = (float)TOTAL / ((float)NDATA * g_sums[0]);
        const float invZs = (float)TOTAL / ((float)NDATA * g_sums[1]);
        float acc = 0.f;
        if (k < KP1) {
            float4 vs = *((const float4*)(g_out_s + b * PAD + k));
            float4 vt = *((const float4*)(g_out_t + b * PAD + k));
            float xs[4] = {vs.x, vs.y, vs.z, vs.w};
            float xt[4] = {vt.x, vt.y, vt.z, vt.w};
            #pragma unroll
            for (int c = 0; c < 4; ++c) {
                if (k + c < KP1) {
                    float xS = xs[c] * invZs;
                    float xT = xt[c] * invZt;
                    if (k + c == 0) {
                        acc += logf(xS / (xS + MPN + EPSF)) + logf(xT / (xT + MPN + EPSF));
                    } else {
                        acc -= logf(1.0f + (xS + EPSF) * (1.0f / MPN));
                        acc -= logf(1.0f + (xT + EPSF) * (1.0f / MPN));
                    }
                }
            }
        }
        #pragma unroll
        for (int o = 16; o; o >>= 1) acc += __shfl_xor_sync(0xffffffffu, acc, o);
        __shared__ float sh[8];
        const int lane = threadIdx.x & 31, w_ = threadIdx.x >> 5;
        if (lane == 0) sh[w_] = acc;
        __syncthreads();
        if (threadIdx.x == 0) {
            float tot = 0.f;
            #pragma unroll
            for (int i = 0; i < 8; ++i) tot += sh[i];
            atomicAdd(&g_sums[2], tot);
            __threadfence();
            int t = atomicAdd(&g_ticket, 1);
            if (t == LOSS_BLOCKS - 1) {
                out[0] = -g_sums[2] / (float)BSZ;
            }
        }
        return;
    }

    const int b = bid - LOSS_BLOCKS;
    const int t = threadIdx.x;
    if (t >= 128) return;
    float* o1 = out + 1;
    float* o2 = out + 1 + MEMELEMS;
    const int row = __ldg(idx + b);
    const size_t off = (size_t)row * FEAT + t;
    float v1 = __ldg(m1 + off) * 0.5f + g_es[b * FEAT + t] * 0.5f;
    float v2 = __ldg(m2 + off) * 0.5f + g_et[b * FEAT + t] * 0.5f;
    float s1 = v1 * v1, s2 = v2 * v2;
    #pragma unroll
    for (int o = 16; o; o >>= 1) {
        s1 += __shfl_xor_sync(0xffffffffu, s1, o);
        s2 += __shfl_xor_sync(0xffffffffu, s2, o);
    }
    __shared__ float sh1[4], sh2[4];
    const int lane = t & 31, w_ = t >> 5;
    if (lane == 0) { sh1[w_] = s1; sh2[w_] = s2; }
    __syncthreads();
    float t1 = sh1[0] + sh1[1] + sh1[2] + sh1[3];
    float t2 = sh2[0] + sh2[1] + sh2[2] + sh2[3];
    o1[off] = v1 / sqrtf(t1);
    o2[off] = v2 / sqrtf(t2);
}

// ---------------------------------------------------------------- launch
extern "C" void kernel_launch(void* const* d_in, const int* in_sizes, int n_in,
                              void* d_out, int out_size) {
    const float* f_s  = (const float*)d_in[0];
    const float* f_t  = (const float*)d_in[1];
    const int*   idx  = (const int*)  d_in[2];
    const int*   cidx = (const int*)  d_in[3];
    const float* W_s  = (const float*)d_in[4];
    const float* b_s  = (const float*)d_in[5];
    const float* W_t  = (const float*)d_in[6];
    const float* b_t  = (const float*)d_in[7];
    const float* m1   = (const float*)d_in[8];
    const float* m2   = (const float*)d_in[9];
    float* out = (float*)d_out;

    embed_partial<<<1024, 128>>>(f_s, f_t, W_s, W_t);
    normalize_kernel<<<512, 128>>>(b_s, b_t);
    nce_kernel<<<4097, 256>>>(cidx, m1, m2);
    copy_kernel<<<15625, 256>>>(m1, m2, out);
    lossup_kernel<<<LOSS_BLOCKS + BSZ, 256>>>(idx, m1, m2, out);
}